// round 3
// baseline (speedup 1.0000x reference)
#include <cuda_runtime.h>
#include <math.h>

// Problem constants (fixed shapes from reference)
#define NQ      262144      // total queries = B*L*cg = 4*1024*64
#define NSAM    1024        // prior samples
#define NPAIR   512         // sample pairs (f32x2 packing)
#define TSTRIDE 16          // floats per pair row in smem table (64 B rows)
#define THREADS 448
#define QPT     2           // queries per thread
#define CHUNK   16          // pairs per argmax chunk
#define NCHUNK  (NPAIR / CHUNK)
#define ZHAT_OFF   0
#define NOQ_OFF    1048576  // B*L*C
#define IDX_OFF    2097152  // 2*B*L*C
#define FULL_OUT   2359296  // + B*L*cg

// ---- packed f32x2 helpers (Blackwell FFMA2/FMUL2) ----
__device__ __forceinline__ unsigned long long ffma2(unsigned long long a,
                                                    unsigned long long b,
                                                    unsigned long long c) {
    unsigned long long d;
    asm("fma.rn.f32x2 %0, %1, %2, %3;" : "=l"(d) : "l"(a), "l"(b), "l"(c));
    return d;
}
__device__ __forceinline__ unsigned long long fmul2(unsigned long long a,
                                                    unsigned long long b) {
    unsigned long long d;
    asm("mul.rn.f32x2 %0, %1, %2;" : "=l"(d) : "l"(a), "l"(b));
    return d;
}
__device__ __forceinline__ unsigned long long pack2(float x) {
    unsigned long long r;
    asm("mov.b64 %0, {%1, %1};" : "=l"(r) : "f"(x));
    return r;
}
__device__ __forceinline__ float lo2(unsigned long long a) {
    return __uint_as_float((unsigned)(a & 0xffffffffull));
}
__device__ __forceinline__ float hi2(unsigned long long a) {
    return __uint_as_float((unsigned)(a >> 32));
}

// Recompute scores of one 16-pair chunk for one query; return first pair index
// whose selected lane equals target exactly (bit-deterministic recompute).
__device__ __forceinline__ int rescan_chunk(const float* __restrict__ tab,
                                            const unsigned long long* uu,
                                            const unsigned long long* vv,
                                            int chunk, float target, int odd) {
    int found = NPAIR;    // min-reduce => first match
    #pragma unroll 4
    for (int t = 0; t < CHUNK; t++) {
        int p = chunk * CHUNK + t;
        const float* base = &tab[p * TSTRIDE];
        ulonglong2 wa = *reinterpret_cast<const ulonglong2*>(base + 0);   // S0,S1
        ulonglong2 wb = *reinterpret_cast<const ulonglong2*>(base + 4);   // S2,S3
        ulonglong2 wc = *reinterpret_cast<const ulonglong2*>(base + 8);   // T0,T1
        ulonglong2 wd = *reinterpret_cast<const ulonglong2*>(base + 12);  // T2,T3
        unsigned long long a = fmul2(uu[0], wa.x);
        a = ffma2(uu[1], wa.y, a);
        a = ffma2(uu[2], wb.x, a);
        a = ffma2(uu[3], wb.y, a);
        a = ffma2(vv[0], wc.x, a);
        a = ffma2(vv[1], wc.y, a);
        a = ffma2(vv[2], wd.x, a);
        a = ffma2(vv[3], wd.y, a);
        float v = odd ? hi2(a) : lo2(a);
        if (v == target) found = min(found, p);
    }
    return found;
}

__global__ void __launch_bounds__(THREADS, 2)
gq_kernel(const float* __restrict__ z,
          const float* __restrict__ eps,
          const float* __restrict__ prior,
          float* __restrict__ out,
          int out_size)
{
    // Packed sample table: per pair p (= samples 2p, 2p+1), 8 f32x2 words:
    //   [S_g0 | S_g1 | S_g2 | S_g3 | T_g0 | T_g1 | T_g2 | T_g3]  (T = -0.5*S^2)
    // The -beta*nlp term c_n = -sum_g T is folded into v' = v - 1 per query.
    __shared__ __align__(16) float tab[NPAIR * TSTRIDE];   // 32768 B per CTA

    const int tid = threadIdx.x;
    for (int n = tid; n < NSAM; n += THREADS) {
        float4 s = reinterpret_cast<const float4*>(prior)[n];
        int p = n >> 1, h = n & 1;
        float* t = &tab[p * TSTRIDE];
        t[0 + h]  = s.x;  t[2 + h]  = s.y;  t[4 + h]  = s.z;  t[6 + h]  = s.w;
        t[8 + h]  = -0.5f * s.x * s.x;
        t[10 + h] = -0.5f * s.y * s.y;
        t[12 + h] = -0.5f * s.z * s.z;
        t[14 + h] = -0.5f * s.w * s.w;
    }

    // Each thread owns 2 consecutive queries k0, k0+1 (j even, never crosses a row)
    const int gtid = blockIdx.x * THREADS + tid;
    const int k0   = gtid * QPT;
    const bool valid = (k0 < NQ);
    const int bl = k0 >> 6;     // (b*L + l)
    const int j  = k0 & 63;

    // Packed per-query coefficients: uu[q][g] = (u,u), vv[q][g] = (v-1, v-1)
    unsigned long long uu[QPT][4], vv[QPT][4];

    if (valid) {
        #pragma unroll
        for (int g = 0; g < 4; g++) {
            const int moff = bl * 512 + g * 64 + j;           // mu
            float2 mu2 = *reinterpret_cast<const float2*>(z + moff);
            float2 lv2 = *reinterpret_cast<const float2*>(z + moff + 256);
            lv2.x = fminf(fmaxf(lv2.x, -30.0f), 20.0f);
            lv2.y = fminf(fmaxf(lv2.y, -30.0f), 20.0f);
            float ivx = expf(-lv2.x), ivy = expf(-lv2.y);
            uu[0][g] = pack2(mu2.x * ivx);  vv[0][g] = pack2(ivx - 1.0f);
            uu[1][g] = pack2(mu2.y * ivy);  vv[1][g] = pack2(ivy - 1.0f);

            // Fused zhat_noquant = mu + eps * exp(0.5*logvar)
            const int eoff = bl * 256 + g * 64 + j;
            float2 e2 = *reinterpret_cast<const float2*>(eps + eoff);
            float2 nq;
            nq.x = fmaf(e2.x, expf(0.5f * lv2.x), mu2.x);
            nq.y = fmaf(e2.y, expf(0.5f * lv2.y), mu2.y);
            if (out_size >= IDX_OFF)
                *reinterpret_cast<float2*>(out + NOQ_OFF + eoff) = nq;
        }
    }
    __syncthreads();
    if (!valid) return;   // tail threads exit (no further barriers)

    const float NEG_INF = -__int_as_float(0x7f800000);
    // Per-stream global chunk-max: [query][lane]
    float g0e = NEG_INF, g0o = NEG_INF, g1e = NEG_INF, g1o = NEG_INF;
    int   c0e = 0, c0o = 0, c1e = 0, c1o = 0;

    for (int ch = 0; ch < NCHUNK; ch++) {
        float m0e = NEG_INF, m0o = NEG_INF, m1e = NEG_INF, m1o = NEG_INF;
        #pragma unroll 4
        for (int t = 0; t < CHUNK; t++) {
            const float* base = &tab[(ch * CHUNK + t) * TSTRIDE];
            ulonglong2 wa = *reinterpret_cast<const ulonglong2*>(base + 0);   // S0,S1
            ulonglong2 wb = *reinterpret_cast<const ulonglong2*>(base + 4);   // S2,S3
            ulonglong2 wc = *reinterpret_cast<const ulonglong2*>(base + 8);   // T0,T1
            ulonglong2 wd = *reinterpret_cast<const ulonglong2*>(base + 12);  // T2,T3

            unsigned long long a0 = fmul2(uu[0][0], wa.x);
            unsigned long long a1 = fmul2(uu[1][0], wa.x);
            a0 = ffma2(uu[0][1], wa.y, a0);  a1 = ffma2(uu[1][1], wa.y, a1);
            a0 = ffma2(uu[0][2], wb.x, a0);  a1 = ffma2(uu[1][2], wb.x, a1);
            a0 = ffma2(uu[0][3], wb.y, a0);  a1 = ffma2(uu[1][3], wb.y, a1);
            a0 = ffma2(vv[0][0], wc.x, a0);  a1 = ffma2(vv[1][0], wc.x, a1);
            a0 = ffma2(vv[0][1], wc.y, a0);  a1 = ffma2(vv[1][1], wc.y, a1);
            a0 = ffma2(vv[0][2], wd.x, a0);  a1 = ffma2(vv[1][2], wd.x, a1);
            a0 = ffma2(vv[0][3], wd.y, a0);  a1 = ffma2(vv[1][3], wd.y, a1);

            m0e = fmaxf(m0e, lo2(a0));  m0o = fmaxf(m0o, hi2(a0));
            m1e = fmaxf(m1e, lo2(a1));  m1o = fmaxf(m1o, hi2(a1));
        }
        // Strict '>' keeps the earliest chunk on ties (first-index semantics)
        if (m0e > g0e) { g0e = m0e; c0e = ch; }
        if (m0o > g0o) { g0o = m0o; c0o = ch; }
        if (m1e > g1e) { g1e = m1e; c1e = ch; }
        if (m1o > g1o) { g1o = m1o; c1o = ch; }
    }

    // Resolve exact indices by rescanning the winning chunk(s)
    int bidx[QPT];
    {
        float ge[QPT] = {g0e, g1e}, go[QPT] = {g0o, g1o};
        int   ce[QPT] = {c0e, c1e}, co[QPT] = {c0o, c1o};
        #pragma unroll
        for (int q = 0; q < QPT; q++) {
            if (go[q] > ge[q]) {
                bidx[q] = 2 * rescan_chunk(tab, uu[q], vv[q], co[q], go[q], 1) + 1;
            } else if (ge[q] > go[q]) {
                bidx[q] = 2 * rescan_chunk(tab, uu[q], vv[q], ce[q], ge[q], 0);
            } else {
                int pe = rescan_chunk(tab, uu[q], vv[q], ce[q], ge[q], 0);
                int po = rescan_chunk(tab, uu[q], vv[q], co[q], go[q], 1);
                bidx[q] = min(2 * pe, 2 * po + 1);   // exact tie: first sample index
            }
        }
    }

    {
        // Gather winning prior rows (prior table is L2-hot, 16 KB)
        float r[QPT][4];
        #pragma unroll
        for (int q = 0; q < QPT; q++) {
            float4 s = reinterpret_cast<const float4*>(prior)[bidx[q]];
            r[q][0] = s.x; r[q][1] = s.y; r[q][2] = s.z; r[q][3] = s.w;
        }
        #pragma unroll
        for (int g = 0; g < 4; g++) {
            float2 o2 = make_float2(r[0][g], r[1][g]);
            *reinterpret_cast<float2*>(out + ZHAT_OFF + bl * 256 + g * 64 + j) = o2;
        }
        if (out_size >= FULL_OUT) {
            float2 i2 = make_float2((float)bidx[0], (float)bidx[1]);
            *reinterpret_cast<float2*>(out + IDX_OFF + k0) = i2;
        }
    }
}

extern "C" void kernel_launch(void* const* d_in, const int* in_sizes, int n_in,
                              void* d_out, int out_size) {
    const float* z     = (const float*)d_in[0];
    const float* eps   = (const float*)d_in[1];
    const float* prior = (const float*)d_in[2];
    (void)in_sizes; (void)n_in;
    const int thread_slots = NQ / QPT;                         // 131072
    const int blocks = (thread_slots + THREADS - 1) / THREADS; // 293 -> 2 CTAs/SM, one wave
    gq_kernel<<<blocks, THREADS>>>(z, eps, prior, (float*)d_out, out_size);
}

// round 4
// speedup vs baseline: 1.2691x; 1.2691x over previous
#include <cuda_runtime.h>
#include <math.h>

// Problem constants (fixed shapes from reference)
#define NQ      262144      // total queries = B*L*cg = 4*1024*64
#define NSAM    1024        // prior samples
#define NPAIR   512         // sample pairs (f32x2 packing)
#define TSTRIDE 8           // floats per pair row in smem table (32 B rows: S only)
#define THREADS 448
#define QPT     2           // queries per thread
#define CHUNK   16          // pairs per argmax chunk
#define NCHUNK  (NPAIR / CHUNK)
#define ZHAT_OFF   0
#define NOQ_OFF    1048576  // B*L*C
#define IDX_OFF    2097152  // 2*B*L*C
#define FULL_OUT   2359296  // + B*L*cg

// ---- packed f32x2 helpers (Blackwell FFMA2/FMUL2) ----
__device__ __forceinline__ unsigned long long ffma2(unsigned long long a,
                                                    unsigned long long b,
                                                    unsigned long long c) {
    unsigned long long d;
    asm("fma.rn.f32x2 %0, %1, %2, %3;" : "=l"(d) : "l"(a), "l"(b), "l"(c));
    return d;
}
__device__ __forceinline__ unsigned long long fmul2(unsigned long long a,
                                                    unsigned long long b) {
    unsigned long long d;
    asm("mul.rn.f32x2 %0, %1, %2;" : "=l"(d) : "l"(a), "l"(b));
    return d;
}
__device__ __forceinline__ unsigned long long pack2(float x) {
    unsigned long long r;
    asm("mov.b64 %0, {%1, %1};" : "=l"(r) : "f"(x));
    return r;
}
__device__ __forceinline__ float lo2(unsigned long long a) {
    return __uint_as_float((unsigned)(a & 0xffffffffull));
}
__device__ __forceinline__ float hi2(unsigned long long a) {
    return __uint_as_float((unsigned)(a >> 32));
}

// Factored score for one query against one sample pair:
//   acc = sum_g S_g * (u_g + vh_g * S_g)
__device__ __forceinline__ unsigned long long score_pair(
        const unsigned long long* uu, const unsigned long long* vh,
        unsigned long long s0, unsigned long long s1,
        unsigned long long s2, unsigned long long s3) {
    unsigned long long t, a;
    t = ffma2(vh[0], s0, uu[0]);  a = fmul2(s0, t);
    t = ffma2(vh[1], s1, uu[1]);  a = ffma2(s1, t, a);
    t = ffma2(vh[2], s2, uu[2]);  a = ffma2(s2, t, a);
    t = ffma2(vh[3], s3, uu[3]);  a = ffma2(s3, t, a);
    return a;
}

// Recompute scores of one chunk for one query; return first pair index whose
// selected lane equals target exactly (bit-deterministic recompute).
__device__ __forceinline__ int rescan_chunk(const float* __restrict__ tab,
                                            const unsigned long long* uu,
                                            const unsigned long long* vh,
                                            int chunk, float target, int odd) {
    int found = NPAIR;    // min-reduce => first match
    #pragma unroll 4
    for (int t = 0; t < CHUNK; t++) {
        int p = chunk * CHUNK + t;
        const float* base = &tab[p * TSTRIDE];
        ulonglong2 wa = *reinterpret_cast<const ulonglong2*>(base + 0);   // S0,S1
        ulonglong2 wb = *reinterpret_cast<const ulonglong2*>(base + 4);   // S2,S3
        unsigned long long a = score_pair(uu, vh, wa.x, wa.y, wb.x, wb.y);
        float v = odd ? hi2(a) : lo2(a);
        if (v == target) found = min(found, p);
    }
    return found;
}

__global__ void __launch_bounds__(THREADS, 2)
gq_kernel(const float* __restrict__ z,
          const float* __restrict__ eps,
          const float* __restrict__ prior,
          float* __restrict__ out,
          int out_size)
{
    // Packed sample table: per pair p (= samples 2p, 2p+1), 4 f32x2 words:
    //   [S_g0 | S_g1 | S_g2 | S_g3]
    // All other terms are folded into per-query coefficients:
    //   u_g = mu*e^{-lv},  vh_g = 0.5*(1 - e^{-lv})
    //   score ~ sum_g S*(u + vh*S)   (per-query/global constants dropped)
    __shared__ __align__(16) float tab[NPAIR * TSTRIDE];   // 16384 B per CTA

    const int tid = threadIdx.x;
    for (int n = tid; n < NSAM; n += THREADS) {
        float4 s = reinterpret_cast<const float4*>(prior)[n];
        int p = n >> 1, h = n & 1;
        float* t = &tab[p * TSTRIDE];
        t[0 + h] = s.x;  t[2 + h] = s.y;  t[4 + h] = s.z;  t[6 + h] = s.w;
    }

    // Each thread owns 2 consecutive queries k0, k0+1 (j even, never crosses a row)
    const int gtid = blockIdx.x * THREADS + tid;
    const int k0   = gtid * QPT;
    const bool valid = (k0 < NQ);
    const int bl = k0 >> 6;     // (b*L + l)
    const int j  = k0 & 63;

    // Packed per-query coefficients
    unsigned long long uu[QPT][4], vh[QPT][4];

    if (valid) {
        #pragma unroll
        for (int g = 0; g < 4; g++) {
            const int moff = bl * 512 + g * 64 + j;           // mu
            float2 mu2 = *reinterpret_cast<const float2*>(z + moff);
            float2 lv2 = *reinterpret_cast<const float2*>(z + moff + 256);
            lv2.x = fminf(fmaxf(lv2.x, -30.0f), 20.0f);
            lv2.y = fminf(fmaxf(lv2.y, -30.0f), 20.0f);
            float ivx = expf(-lv2.x), ivy = expf(-lv2.y);
            uu[0][g] = pack2(mu2.x * ivx);  vh[0][g] = pack2(0.5f * (1.0f - ivx));
            uu[1][g] = pack2(mu2.y * ivy);  vh[1][g] = pack2(0.5f * (1.0f - ivy));

            // Fused zhat_noquant = mu + eps * exp(0.5*logvar)
            const int eoff = bl * 256 + g * 64 + j;
            float2 e2 = *reinterpret_cast<const float2*>(eps + eoff);
            float2 nq;
            nq.x = fmaf(e2.x, expf(0.5f * lv2.x), mu2.x);
            nq.y = fmaf(e2.y, expf(0.5f * lv2.y), mu2.y);
            if (out_size >= IDX_OFF)
                *reinterpret_cast<float2*>(out + NOQ_OFF + eoff) = nq;
        }
    }
    __syncthreads();
    if (!valid) return;   // tail threads exit (no further barriers)

    const float NEG_INF = -__int_as_float(0x7f800000);
    float g0e = NEG_INF, g0o = NEG_INF, g1e = NEG_INF, g1o = NEG_INF;
    int   c0e = 0, c0o = 0, c1e = 0, c1o = 0;

    for (int ch = 0; ch < NCHUNK; ch++) {
        float m0e = NEG_INF, m0o = NEG_INF, m1e = NEG_INF, m1o = NEG_INF;
        #pragma unroll
        for (int t = 0; t < CHUNK; t++) {
            const float* base = &tab[(ch * CHUNK + t) * TSTRIDE];
            ulonglong2 wa = *reinterpret_cast<const ulonglong2*>(base + 0);   // S0,S1
            ulonglong2 wb = *reinterpret_cast<const ulonglong2*>(base + 4);   // S2,S3

            unsigned long long t0, t1, a0, a1;
            t0 = ffma2(vh[0][0], wa.x, uu[0][0]);  t1 = ffma2(vh[1][0], wa.x, uu[1][0]);
            a0 = fmul2(wa.x, t0);                  a1 = fmul2(wa.x, t1);
            t0 = ffma2(vh[0][1], wa.y, uu[0][1]);  t1 = ffma2(vh[1][1], wa.y, uu[1][1]);
            a0 = ffma2(wa.y, t0, a0);              a1 = ffma2(wa.y, t1, a1);
            t0 = ffma2(vh[0][2], wb.x, uu[0][2]);  t1 = ffma2(vh[1][2], wb.x, uu[1][2]);
            a0 = ffma2(wb.x, t0, a0);              a1 = ffma2(wb.x, t1, a1);
            t0 = ffma2(vh[0][3], wb.y, uu[0][3]);  t1 = ffma2(vh[1][3], wb.y, uu[1][3]);
            a0 = ffma2(wb.y, t0, a0);              a1 = ffma2(wb.y, t1, a1);

            m0e = fmaxf(m0e, lo2(a0));  m0o = fmaxf(m0o, hi2(a0));
            m1e = fmaxf(m1e, lo2(a1));  m1o = fmaxf(m1o, hi2(a1));
        }
        // Strict '>' keeps the earliest chunk on ties (first-index semantics)
        if (m0e > g0e) { g0e = m0e; c0e = ch; }
        if (m0o > g0o) { g0o = m0o; c0o = ch; }
        if (m1e > g1e) { g1e = m1e; c1e = ch; }
        if (m1o > g1o) { g1o = m1o; c1o = ch; }
    }

    // Resolve exact indices by rescanning the winning chunk(s)
    int bidx[QPT];
    {
        float ge[QPT] = {g0e, g1e}, go[QPT] = {g0o, g1o};
        int   ce[QPT] = {c0e, c1e}, co[QPT] = {c0o, c1o};
        #pragma unroll
        for (int q = 0; q < QPT; q++) {
            if (go[q] > ge[q]) {
                bidx[q] = 2 * rescan_chunk(tab, uu[q], vh[q], co[q], go[q], 1) + 1;
            } else if (ge[q] > go[q]) {
                bidx[q] = 2 * rescan_chunk(tab, uu[q], vh[q], ce[q], ge[q], 0);
            } else {
                int pe = rescan_chunk(tab, uu[q], vh[q], ce[q], ge[q], 0);
                int po = rescan_chunk(tab, uu[q], vh[q], co[q], go[q], 1);
                bidx[q] = min(2 * pe, 2 * po + 1);   // exact tie: first sample index
            }
        }
    }

    {
        // Gather winning prior rows (prior table is L2-hot, 16 KB)
        float r[QPT][4];
        #pragma unroll
        for (int q = 0; q < QPT; q++) {
            float4 s = reinterpret_cast<const float4*>(prior)[bidx[q]];
            r[q][0] = s.x; r[q][1] = s.y; r[q][2] = s.z; r[q][3] = s.w;
        }
        #pragma unroll
        for (int g = 0; g < 4; g++) {
            float2 o2 = make_float2(r[0][g], r[1][g]);
            *reinterpret_cast<float2*>(out + ZHAT_OFF + bl * 256 + g * 64 + j) = o2;
        }
        if (out_size >= FULL_OUT) {
            float2 i2 = make_float2((float)bidx[0], (float)bidx[1]);
            *reinterpret_cast<float2*>(out + IDX_OFF + k0) = i2;
        }
    }
}

extern "C" void kernel_launch(void* const* d_in, const int* in_sizes, int n_in,
                              void* d_out, int out_size) {
    const float* z     = (const float*)d_in[0];
    const float* eps   = (const float*)d_in[1];
    const float* prior = (const float*)d_in[2];
    (void)in_sizes; (void)n_in;
    const int thread_slots = NQ / QPT;                         // 131072
    const int blocks = (thread_slots + THREADS - 1) / THREADS; // 293 -> 2 CTAs/SM, one wave
    gq_kernel<<<blocks, THREADS>>>(z, eps, prior, (float*)d_out, out_size);
}